// round 15
// baseline (speedup 1.0000x reference)
#include <cuda_runtime.h>
#include <cuda_fp16.h>
#include <cstdint>

#define BB 512
#define TT 128
#define CC 512
#define HH 8
#define LL 6
#define VV 13
#define DD 64
#define MM (BB*TT)

// ---------------- scratch arena (static, no allocation) ----------------
#define OFF_X    ((size_t)0)
#define SZ_X     ((size_t)MM*CC*4)
#define OFF_QKVH (OFF_X + SZ_X)
#define SZ_QKVH  ((size_t)MM*1536*2)
#define OFF_Y    (OFF_QKVH + SZ_QKVH)
#define OFF_XH   (OFF_Y + SZ_X)
#define SZ_AH    ((size_t)MM*CC*2)
#define OFF_HHI  (OFF_XH + SZ_AH)
#define OFF_WH   (OFF_HHI + SZ_AH)
#define SZ_W     ((size_t)24*512*512*2)
#define OFF_BQKV (OFF_WH + SZ_W)
#define SCRATCH_BYTES (OFF_BQKV + (size_t)LL*1536*4)

__device__ __align__(1024) unsigned char g_scratch[SCRATCH_BYTES];

// ---------------- helpers ----------------
__device__ __forceinline__ uint32_t smem_u32(const void* p) {
    uint32_t a;
    asm("{ .reg .u64 t; cvta.to.shared.u64 t, %1; cvt.u32.u64 %0, t; }" : "=r"(a) : "l"(p));
    return a;
}
__device__ __forceinline__ void cpa16(uint32_t dst, const void* src) {
    asm volatile("cp.async.cg.shared.global [%0], [%1], 16;" :: "r"(dst), "l"(src));
}
__device__ __forceinline__ void cpa_commit() {
    asm volatile("cp.async.commit_group;");
}
template<int OFF>
__device__ __forceinline__ uint4 lds128o(uint32_t base) {
    uint4 v;
    asm volatile("ld.shared.v4.b32 {%0,%1,%2,%3}, [%4+%5];"
                 : "=r"(v.x), "=r"(v.y), "=r"(v.z), "=r"(v.w) : "r"(base), "n"(OFF));
    return v;
}
__device__ __forceinline__ void mma16816(float* c, const uint32_t* a, uint32_t b0, uint32_t b1) {
    asm volatile(
        "mma.sync.aligned.m16n8k16.row.col.f32.f16.f16.f32 "
        "{%0,%1,%2,%3}, {%4,%5,%6,%7}, {%8,%9}, {%0,%1,%2,%3};"
        : "+f"(c[0]), "+f"(c[1]), "+f"(c[2]), "+f"(c[3])
        : "r"(a[0]), "r"(a[1]), "r"(a[2]), "r"(a[3]), "r"(b0), "r"(b1));
}
__device__ __forceinline__ uint32_t pk2(float a, float b) {
    __half2 h2 = __floats2half2_rn(a, b);
    return *reinterpret_cast<uint32_t*>(&h2);
}
__device__ __forceinline__ float2 up2(uint32_t u) {
    return __half22float2(*reinterpret_cast<__half2*>(&u));
}
__device__ __forceinline__ int permw(int w) {
    return (w & ~15) + ((w & 3) << 2) + ((w & 15) >> 2);
}

// ---------------- templated GEMM geometry ----------------
// NF = B sub-tiles per warp (8 cols each). Warp tile = 64 x (8*NF).
// CTA tile = 128 x (32*NF). A tile 8KB; B tile = 32*NF rows x 64B.
#define ABYTES 8192

template<int NF> struct Geo {
    static const int NTILE   = 32 * NF;            // CTA n-tile
    static const int BT_B    = NTILE * 64;         // B tile bytes per 32-K
    static const int SUB_B   = ABYTES + BT_B;      // one 32-K sub-stage
    static const int MST_B   = 2 * SUB_B;          // macro-stage (64-K)
    static const int SMEM_B  = 2 * MST_B;          // double buffered
    static const int WLOADS  = NTILE / 64;         // W cp.async rows blocks
};

// One 32-K tile's worth of MMA work; ST = compile-time byte offset of sub-stage.
template<int ST, int NF>
__device__ __forceinline__ void compute_stage(uint32_t aB, uint32_t bB, float acc[4][NF][4]) {
    uint4 bh[NF];
    #pragma unroll
    for (int nf = 0; nf < NF; nf++) {
        switch (nf) {   // compile-time immediate offsets
            case 0: bh[0] = lds128o<ST +    0>(bB); break;
            case 1: bh[1] = lds128o<ST +  512>(bB); break;
            case 2: bh[2] = lds128o<ST + 1024>(bB); break;
            case 3: bh[3] = lds128o<ST + 1536>(bB); break;
            case 4: bh[4] = lds128o<ST + 2048>(bB); break;
            case 5: bh[5] = lds128o<ST + 2560>(bB); break;
        }
    }
#define MFBLOCK(MF)                                                                  \
    {                                                                                \
        uint4 a0 = lds128o<ST + MF * 1024>(aB);                                      \
        uint4 a1 = lds128o<ST + MF * 1024 + 512>(aB);                                \
        uint32_t ak0[4] = {a0.x, a1.x, a0.y, a1.y};                                  \
        uint32_t ak1[4] = {a0.z, a1.z, a0.w, a1.w};                                  \
        _Pragma("unroll")                                                            \
        for (int nf = 0; nf < NF; nf++) {                                            \
            mma16816(acc[MF][nf], ak0, bh[nf].x, bh[nf].y);                          \
            mma16816(acc[MF][nf], ak1, bh[nf].z, bh[nf].w);                          \
        }                                                                            \
    }
    MFBLOCK(0) MFBLOCK(1) MFBLOCK(2) MFBLOCK(3)
#undef MFBLOCK
}

// ---------------- weight prep: Wt[m][n][k] = W_m[k][n], fp16, K-permuted ----------------
__global__ void prep_w(const float* __restrict__ Wq, const float* __restrict__ Wk,
                       const float* __restrict__ Wv, const float* __restrict__ Wo,
                       __half* __restrict__ wh) {
    __shared__ float tile[32][33];
    int m = blockIdx.z;
    int l = m >> 2, type = m & 3;
    const float* W = (type == 0 ? Wq : type == 1 ? Wk : type == 2 ? Wv : Wo) + (size_t)l * CC * CC;
    int k0 = blockIdx.x * 32, n0 = blockIdx.y * 32;
    int tx = threadIdx.x, ty = threadIdx.y;
    #pragma unroll
    for (int r = 0; r < 4; r++) {
        int k = ty + r * 8;
        tile[k][tx] = W[(size_t)(k0 + k) * CC + n0 + tx];
    }
    __syncthreads();
    #pragma unroll
    for (int r = 0; r < 4; r++) {
        int i = ty + r * 8;
        float v = tile[tx][i];
        size_t row = (size_t)m * 512 + n0 + i;
        int kk = k0 + tx;
        int ph = permw(kk >> 1) * 2 + (kk & 1);
        wh[row * 512 + ph] = __float2half_rn(v);
    }
}

__global__ void pack_b(const float* __restrict__ bq, const float* __restrict__ bk,
                       const float* __restrict__ bv, float* __restrict__ bqkv) {
    int idx = blockIdx.x * 1024 + threadIdx.x;
    if (idx >= LL * 1536) return;
    int l = idx / 1536, r = idx % 1536;
    bqkv[idx] = (r < 512) ? bq[l * 512 + r] : (r < 1024) ? bk[l * 512 + r - 512] : bv[l * 512 + r - 1024];
}

// ---------------- embedding (+ permuted fp16 copy) ----------------
__global__ void embed_kernel(const int* __restrict__ tok, const float* __restrict__ wte,
                             const float* __restrict__ wpe, float* __restrict__ x,
                             __half* __restrict__ xh) {
    int row = blockIdx.x;
    int tid = threadIdx.x;
    int tkn = __ldg(tok + row);
    int t = row & (TT - 1);
    float4 a = ((const float4*)(wte + (size_t)tkn * CC))[tid];
    float4 p = ((const float4*)(wpe + (size_t)t * CC))[tid];
    float4 o;
    o.x = a.x + p.x; o.y = a.y + p.y; o.z = a.z + p.z; o.w = a.w + p.w;
    ((float4*)(x + (size_t)row * CC))[tid] = o;
    uint32_t* hp = (uint32_t*)(xh + (size_t)row * CC);
    hp[permw(2 * tid)]     = pk2(o.x, o.y);
    hp[permw(2 * tid + 1)] = pk2(o.z, o.w);
}

// ---------------- single-pass fp16 HMMA GEMM, BK=64 macro-chunks, templated N-tile ----------------
template<int NF>
__global__ __launch_bounds__(256, 2)
void gemm_mma(const __half* __restrict__ A, const __half* __restrict__ Wh,
              int w_row_base, const float* __restrict__ bias, const float* __restrict__ res,
              float* __restrict__ out, __half* __restrict__ outh, int ldout) {
    extern __shared__ unsigned char smem_raw[];
    const int tid = threadIdx.x;
    const int lane = tid & 31;
    const int wid = tid >> 5;
    const int g = lane >> 2, tg = lane & 3;
    const int warp_m = wid & 1;
    const int warp_n = wid >> 1;
    const int mbase = blockIdx.y * 128;
    const int nb = blockIdx.x * Geo<NF>::NTILE;

    const uint32_t sbase = smem_u32(smem_raw);

    // cp.async loader: thread -> rows (r0 + 64j) x one swizzled 16B chunk per tile
    const int r0 = tid >> 2;
    const int c16 = tid & 3;
    const uint32_t so0 = sbase + (uint32_t)(r0 * 64) + (uint32_t)((c16 ^ (r0 & 3)) << 4);
    const size_t arow0 = (size_t)(mbase + r0) * 512 + c16 * 8;
    const size_t wrow0 = (size_t)(w_row_base + nb + r0) * 512 + c16 * 8;

    // fragment bases (loop-invariant)
    const uint32_t axor = (uint32_t)((tg ^ (g & 3)) << 4);
    const uint32_t aBase = sbase + (uint32_t)((warp_m * 64 + g) * 64) + axor;
    const uint32_t bBase = sbase + ABYTES + (uint32_t)((warp_n * (NF * 8) + g) * 64) + axor;

    float acc[4][NF][4];
    #pragma unroll
    for (int i = 0; i < 4; i++)
        #pragma unroll
        for (int j = 0; j < NF; j++)
            #pragma unroll
            for (int q = 0; q < 4; q++) acc[i][j][q] = 0.f;

    auto issue = [&](int buf, int mc) {
        const int k0 = mc * 64;
        const uint32_t sb = so0 + (uint32_t)buf * Geo<NF>::MST_B;
        #pragma unroll
        for (int half = 0; half < 2; half++) {
            const uint32_t hb = sb + (uint32_t)half * Geo<NF>::SUB_B;
            const int kh = k0 + half * 32;
            cpa16(hb,        A + arow0 + kh);
            cpa16(hb + 4096, A + arow0 + 64 * 512 + kh);
            #pragma unroll
            for (int r = 0; r < Geo<NF>::WLOADS; r++)
                cpa16(hb + ABYTES + (uint32_t)r * 4096, Wh + wrow0 + (size_t)r * 64 * 512 + kh);
        }
        cpa_commit();
    };

    issue(0, 0);
    issue(1, 1);

    #pragma unroll 1
    for (int cc = 0; cc < 4; cc++) {
        asm volatile("cp.async.wait_group 1;");
        __syncthreads();
        compute_stage<0, NF>(aBase, bBase, acc);
        compute_stage<Geo<NF>::SUB_B, NF>(aBase, bBase, acc);
        __syncthreads();
        if (cc < 3) issue(0, 2 * cc + 2);
        if (cc < 3) asm volatile("cp.async.wait_group 1;");
        else        asm volatile("cp.async.wait_group 0;");
        __syncthreads();
        compute_stage<Geo<NF>::MST_B, NF>(aBase, bBase, acc);
        compute_stage<Geo<NF>::MST_B + Geo<NF>::SUB_B, NF>(aBase, bBase, acc);
        __syncthreads();
        if (cc < 3) issue(1, 2 * cc + 3);
    }

    // --- epilogue ---
    if (outh) {
        #pragma unroll
        for (int nf = 0; nf < NF; nf++) {
            int col = nb + warp_n * (NF * 8) + nf * 8 + tg * 2;
            float2 b2 = *(const float2*)(bias + col);
            #pragma unroll
            for (int mf = 0; mf < 4; mf++) {
                int row = mbase + warp_m * 64 + mf * 16 + g;
                *(uint32_t*)(outh + (size_t)row * ldout + col) =
                    pk2(acc[mf][nf][0] + b2.x, acc[mf][nf][1] + b2.y);
                *(uint32_t*)(outh + (size_t)(row + 8) * ldout + col) =
                    pk2(acc[mf][nf][2] + b2.x, acc[mf][nf][3] + b2.y);
            }
        }
    } else {
        #pragma unroll
        for (int nf = 0; nf < NF; nf++) {
            int col = nb + warp_n * (NF * 8) + nf * 8 + tg * 2;
            float2 b2 = *(const float2*)(bias + col);
            #pragma unroll
            for (int mf = 0; mf < 4; mf++) {
                int row = mbase + warp_m * 64 + mf * 16 + g;
                float2 o0, o1;
                o0.x = acc[mf][nf][0] + b2.x; o0.y = acc[mf][nf][1] + b2.y;
                o1.x = acc[mf][nf][2] + b2.x; o1.y = acc[mf][nf][3] + b2.y;
                if (res) {
                    float2 r0v = *(const float2*)(res + (size_t)row * CC + col);
                    float2 r1v = *(const float2*)(res + (size_t)(row + 8) * CC + col);
                    o0.x += r0v.x; o0.y += r0v.y;
                    o1.x += r1v.x; o1.y += r1v.y;
                }
                *(float2*)(out + (size_t)row * ldout + col) = o0;
                *(float2*)(out + (size_t)(row + 8) * ldout + col) = o1;
            }
        }
    }
}

// ---------------- attention: one warp per position, syncwarp only ----------------
__global__ __launch_bounds__(256)
void attn_kernel(const __half* __restrict__ qkv, __half* __restrict__ hh) {
    __shared__ uint32_t sq[8][784];
    int w = threadIdx.x >> 5;
    int l = threadIdx.x & 31;
    int r = blockIdx.x * 8 + w;

    const uint32_t* src = (const uint32_t*)(qkv + (size_t)r * 1536);
    uint32_t* s = sq[w];
    #pragma unroll
    for (int it = 0; it < 8; it++)
        s[it * 33 + l] = src[it * 32 + l];
    #pragma unroll
    for (int it = 0; it < 8; it++)
        s[264 + it * 33 + l] = src[256 + it * 32 + l];
    #pragma unroll
    for (int it = 0; it < 8; it++)
        s[528 + it * 32 + l] = src[512 + it * 32 + l];
    __syncwarp();

    int g = l & 7, hb = l >> 3;
    float s1 = 0.f, s2 = 0.f;
    #pragma unroll
    for (int i = 0; i < 32; i++) {
        float2 kf = up2(s[264 + g * 33 + i]);
        float2 q1 = up2(s[hb * 33 + i]);
        float2 q2 = up2(s[(hb + 4) * 33 + i]);
        s1 += q1.x * kf.x + q1.y * kf.y;
        s2 += q2.x * kf.x + q2.y * kf.y;
    }
    s1 *= 0.125f; s2 *= 0.125f;

    float m1 = s1, m2 = s2;
    #pragma unroll
    for (int o = 1; o < 8; o <<= 1) {
        m1 = fmaxf(m1, __shfl_xor_sync(0xffffffffu, m1, o, 8));
        m2 = fmaxf(m2, __shfl_xor_sync(0xffffffffu, m2, o, 8));
    }
    float e1 = expf(s1 - m1), e2 = expf(s2 - m2);
    float t1 = e1, t2 = e2;
    #pragma unroll
    for (int o = 1; o < 8; o <<= 1) {
        t1 += __shfl_xor_sync(0xffffffffu, t1, o, 8);
        t2 += __shfl_xor_sync(0xffffffffu, t2, o, 8);
    }
    float a1 = e1 / t1, a2 = e2 / t2;

    float acc1[8] = {0,0,0,0,0,0,0,0}, acc2[8] = {0,0,0,0,0,0,0,0};
    #pragma unroll
    for (int g2 = 0; g2 < 8; g2++) {
        float b1 = __shfl_sync(0xffffffffu, a1, g2, 8);
        float b2 = __shfl_sync(0xffffffffu, a2, g2, 8);
        #pragma unroll
        for (int jj = 0; jj < 4; jj++) {
            float2 vf = up2(s[528 + g2 * 32 + g * 4 + jj]);
            acc1[2 * jj]     += b1 * vf.x;
            acc1[2 * jj + 1] += b1 * vf.y;
            acc2[2 * jj]     += b2 * vf.x;
            acc2[2 * jj + 1] += b2 * vf.y;
        }
    }

    uint32_t* hbase = (uint32_t*)(hh + (size_t)r * CC);
    uint32_t* hp1 = hbase + (hb * 2 + (g >> 2)) * 16 + (g & 3);
    hp1[0]  = pk2(acc1[0], acc1[1]);
    hp1[4]  = pk2(acc1[2], acc1[3]);
    hp1[8]  = pk2(acc1[4], acc1[5]);
    hp1[12] = pk2(acc1[6], acc1[7]);
    uint32_t* hp2 = hbase + ((hb + 4) * 2 + (g >> 2)) * 16 + (g & 3);
    hp2[0]  = pk2(acc2[0], acc2[1]);
    hp2[4]  = pk2(acc2[2], acc2[3]);
    hp2[8]  = pk2(acc2[4], acc2[5]);
    hp2[12] = pk2(acc2[6], acc2[7]);
}

// ---------------- LayerNorm (warp/row) with permuted fp16 copy ----------------
__global__ void ln_kernel(const float* __restrict__ y, const float* __restrict__ g,
                          const float* __restrict__ b, float* __restrict__ xo,
                          __half* __restrict__ xh) {
    int warp = threadIdx.x >> 5;
    int lane = threadIdx.x & 31;
    size_t row = (size_t)blockIdx.x * 8 + warp;

    const float4* yp = (const float4*)(y + row * CC);
    float4 v[4];
    float s = 0.f, s2 = 0.f;
    #pragma unroll
    for (int i = 0; i < 4; i++) {
        v[i] = yp[lane + 32 * i];
        s  += v[i].x + v[i].y + v[i].z + v[i].w;
        s2 += v[i].x * v[i].x + v[i].y * v[i].y + v[i].z * v[i].z + v[i].w * v[i].w;
    }
    #pragma unroll
    for (int o = 16; o; o >>= 1) {
        s  += __shfl_xor_sync(0xffffffffu, s, o);
        s2 += __shfl_xor_sync(0xffffffffu, s2, o);
    }
    float mean = s * (1.f / 512.f);
    float var = s2 * (1.f / 512.f) - mean * mean;
    float rstd = rsqrtf(var + 1e-5f);

    float4* xp = (float4*)(xo + row * CC);
    uint32_t* hp = (uint32_t*)(xh + row * CC);
    const float4* gp = (const float4*)g;
    const float4* bp = (const float4*)b;
    #pragma unroll
    for (int i = 0; i < 4; i++) {
        int i2 = lane + 32 * i;
        float4 gg = gp[i2], bb = bp[i2], o;
        o.x = (v[i].x - mean) * rstd * gg.x + bb.x;
        o.y = (v[i].y - mean) * rstd * gg.y + bb.y;
        o.z = (v[i].z - mean) * rstd * gg.z + bb.z;
        o.w = (v[i].w - mean) * rstd * gg.w + bb.w;
        xp[i2] = o;
        hp[permw(2 * i2)]     = pk2(o.x, o.y);
        hp[permw(2 * i2 + 1)] = pk2(o.z, o.w);
    }
}

// ---------------- LM head + loss ----------------
__global__ void lmhead_kernel(const float* __restrict__ x, const float* __restrict__ Wlm,
                              const float* __restrict__ blm, float* __restrict__ logits) {
    int warp = threadIdx.x >> 5;
    int lane = threadIdx.x & 31;
    size_t row = (size_t)blockIdx.x * 8 + warp;

    float p[VV];
    #pragma unroll
    for (int vv = 0; vv < VV; vv++) p[vv] = 0.f;
    const float* xr = x + row * CC;
    for (int kk = lane; kk < CC; kk += 32) {
        float xv = xr[kk];
        const float* wrow = Wlm + (size_t)kk * VV;
        #pragma unroll
        for (int vv = 0; vv < VV; vv++) p[vv] += xv * wrow[vv];
    }
    #pragma unroll
    for (int vv = 0; vv < VV; vv++)
        #pragma unroll
        for (int o = 16; o; o >>= 1) p[vv] += __shfl_xor_sync(0xffffffffu, p[vv], o);
    if (lane == 0) {
        float* lp = logits + row * VV;
        #pragma unroll
        for (int vv = 0; vv < VV; vv++) lp[vv] = p[vv] + blm[vv];
    }
}

__global__ void loss_kernel(const float* __restrict__ logits, const int* __restrict__ label,
                            float* __restrict__ out_loss) {
    __shared__ float sdata[512];
    int b = threadIdx.x;
    const float* lg = logits + ((size_t)b * TT + (TT - 1)) * VV;
    float m = lg[0];
    #pragma unroll
    for (int vv = 1; vv < VV; vv++) m = fmaxf(m, lg[vv]);
    float s = 0.f;
    #pragma unroll
    for (int vv = 0; vv < VV; vv++) s += expf(lg[vv] - m);
    float lse = m + logf(s);
    sdata[b] = -(lg[label[b]] - lse);
    __syncthreads();
    for (int st = 256; st; st >>= 1) {
        if (b < st) sdata[b] += sdata[b + st];
        __syncthreads();
    }
    if (b == 0) *out_loss = sdata[0] * (1.f / BB);
}

// ---------------- host ----------------
extern "C" void kernel_launch(void* const* d_in, const int* in_sizes, int n_in,
                              void* d_out, int out_size) {
    const int*   tok   = (const int*)d_in[0];
    const int*   label = (const int*)d_in[1];
    const float* wte   = (const float*)d_in[2];
    const float* wpe   = (const float*)d_in[3];
    const float* Wq    = (const float*)d_in[4];
    const float* bq    = (const float*)d_in[5];
    const float* Wk    = (const float*)d_in[6];
    const float* bk    = (const float*)d_in[7];
    const float* Wv    = (const float*)d_in[8];
    const float* bv    = (const float*)d_in[9];
    const float* Wo    = (const float*)d_in[10];
    const float* bo    = (const float*)d_in[11];
    const float* ln_g  = (const float*)d_in[12];
    const float* ln_b  = (const float*)d_in[13];
    const float* Wlm   = (const float*)d_in[14];
    const float* blm   = (const float*)d_in[15];
    float* out = (float*)d_out;

    unsigned char* base = nullptr;
    cudaGetSymbolAddress((void**)&base, g_scratch);
    float* x     = (float*)(base + OFF_X);
    __half* qkvh = (__half*)(base + OFF_QKVH);
    float* y     = (float*)(base + OFF_Y);
    __half* xh   = (__half*)(base + OFF_XH);
    __half* hh   = (__half*)(base + OFF_HHI);
    __half* wh   = (__half*)(base + OFF_WH);
    float* bqkv  = (float*)(base + OFF_BQKV);

    static bool attr_set = false;
    if (!attr_set) {
        cudaFuncSetAttribute(gemm_mma<6>, cudaFuncAttributeMaxDynamicSharedMemorySize, Geo<6>::SMEM_B);
        cudaFuncSetAttribute(gemm_mma<4>, cudaFuncAttributeMaxDynamicSharedMemorySize, Geo<4>::SMEM_B);
        attr_set = true;
    }

    prep_w<<<dim3(16, 16, 24), dim3(32, 8)>>>(Wq, Wk, Wv, Wo, wh);
    pack_b<<<9, 1024>>>(bq, bk, bv, bqkv);

    embed_kernel<<<MM, 128>>>(tok, wte, wpe, x, xh);

    for (int l = 0; l < LL; l++) {
        gemm_mma<6><<<dim3(1536 / Geo<6>::NTILE, MM / 128), 256, Geo<6>::SMEM_B>>>(xh, wh,
            l * 2048, bqkv + l * 1536, nullptr, nullptr, qkvh, 1536);
        attn_kernel<<<MM / 8, 256>>>(qkvh, hh);
        gemm_mma<4><<<dim3(512 / Geo<4>::NTILE, MM / 128), 256, Geo<4>::SMEM_B>>>(hh, wh,
            l * 2048 + 1536, bo + l * 512, x, y, nullptr, 512);
        ln_kernel<<<MM / 8, 256>>>(y, ln_g + (size_t)l * CC, ln_b + (size_t)l * CC, x, xh);
    }

    lmhead_kernel<<<MM / 8, 256>>>(x, Wlm, blm, out);
    if (out_size >= MM * VV + 1)
        loss_kernel<<<1, 512>>>(out, label, out + (MM * VV));
}

// round 16
// speedup vs baseline: 1.1249x; 1.1249x over previous
#include <cuda_runtime.h>
#include <cuda_fp16.h>
#include <cstdint>

#define BB 512
#define TT 128
#define CC 512
#define HH 8
#define LL 6
#define VV 13
#define DD 64
#define MM (BB*TT)

// ---------------- scratch arena (static, no allocation) ----------------
#define OFF_X    ((size_t)0)
#define SZ_X     ((size_t)MM*CC*4)
#define OFF_QKVH (OFF_X + SZ_X)
#define SZ_QKVH  ((size_t)MM*1536*2)
#define OFF_Y    (OFF_QKVH + SZ_QKVH)
#define OFF_XH   (OFF_Y + SZ_X)
#define SZ_AH    ((size_t)MM*CC*2)
#define OFF_HHI  (OFF_XH + SZ_AH)
#define OFF_WH   (OFF_HHI + SZ_AH)
#define SZ_W     ((size_t)24*512*512*2)
#define OFF_BQKV (OFF_WH + SZ_W)
#define SCRATCH_BYTES (OFF_BQKV + (size_t)LL*1536*4)

__device__ __align__(1024) unsigned char g_scratch[SCRATCH_BYTES];

// ---------------- helpers ----------------
__device__ __forceinline__ uint32_t smem_u32(const void* p) {
    uint32_t a;
    asm("{ .reg .u64 t; cvta.to.shared.u64 t, %1; cvt.u32.u64 %0, t; }" : "=r"(a) : "l"(p));
    return a;
}
__device__ __forceinline__ void cpa16(uint32_t dst, const void* src) {
    asm volatile("cp.async.cg.shared.global [%0], [%1], 16;" :: "r"(dst), "l"(src));
}
__device__ __forceinline__ void cpa_commit() {
    asm volatile("cp.async.commit_group;");
}
template<int OFF>
__device__ __forceinline__ uint4 lds128o(uint32_t base) {
    uint4 v;
    asm volatile("ld.shared.v4.b32 {%0,%1,%2,%3}, [%4+%5];"
                 : "=r"(v.x), "=r"(v.y), "=r"(v.z), "=r"(v.w) : "r"(base), "n"(OFF));
    return v;
}
__device__ __forceinline__ void mma16816(float* c, uint32_t a0, uint32_t a1, uint32_t a2, uint32_t a3,
                                         uint32_t b0, uint32_t b1) {
    asm volatile(
        "mma.sync.aligned.m16n8k16.row.col.f32.f16.f16.f32 "
        "{%0,%1,%2,%3}, {%4,%5,%6,%7}, {%8,%9}, {%0,%1,%2,%3};"
        : "+f"(c[0]), "+f"(c[1]), "+f"(c[2]), "+f"(c[3])
        : "r"(a0), "r"(a1), "r"(a2), "r"(a3), "r"(b0), "r"(b1));
}
__device__ __forceinline__ uint32_t pk2(float a, float b) {
    __half2 h2 = __floats2half2_rn(a, b);
    return *reinterpret_cast<uint32_t*>(&h2);
}
__device__ __forceinline__ float2 up2(uint32_t u) {
    return __half22float2(*reinterpret_cast<__half2*>(&u));
}
__device__ __forceinline__ int permw(int w) {
    return (w & ~15) + ((w & 3) << 2) + ((w & 15) >> 2);
}

// A-only smem pipeline: sub-stage 8KB (one 32-K A tile), macro 16KB, double buffered
#define ASUB_B  8192
#define AMST_B  16384
#define GEMM_SMEM (2*AMST_B)   // 32 KB

// One 32-K tile's MMA work; A from smem (compile-time offset ST), B from registers.
template<int ST>
__device__ __forceinline__ void compute_stage(uint32_t aB, const uint4 bh[4], float acc[4][4][4]) {
#define MFBLOCK(MF)                                                                  \
    {                                                                                \
        uint4 a0 = lds128o<ST + MF * 1024>(aB);                                      \
        uint4 a1 = lds128o<ST + MF * 1024 + 512>(aB);                                \
        _Pragma("unroll")                                                            \
        for (int nf = 0; nf < 4; nf++) {                                             \
            mma16816(acc[MF][nf], a0.x, a1.x, a0.y, a1.y, bh[nf].x, bh[nf].y);       \
            mma16816(acc[MF][nf], a0.z, a1.z, a0.w, a1.w, bh[nf].z, bh[nf].w);       \
        }                                                                            \
    }
    MFBLOCK(0) MFBLOCK(1) MFBLOCK(2) MFBLOCK(3)
#undef MFBLOCK
}

// ---------------- weight prep: Wt[m][n][k] = W_m[k][n], fp16, K-permuted ----------------
__global__ void prep_w(const float* __restrict__ Wq, const float* __restrict__ Wk,
                       const float* __restrict__ Wv, const float* __restrict__ Wo,
                       __half* __restrict__ wh) {
    __shared__ float tile[32][33];
    int m = blockIdx.z;
    int l = m >> 2, type = m & 3;
    const float* W = (type == 0 ? Wq : type == 1 ? Wk : type == 2 ? Wv : Wo) + (size_t)l * CC * CC;
    int k0 = blockIdx.x * 32, n0 = blockIdx.y * 32;
    int tx = threadIdx.x, ty = threadIdx.y;
    #pragma unroll
    for (int r = 0; r < 4; r++) {
        int k = ty + r * 8;
        tile[k][tx] = W[(size_t)(k0 + k) * CC + n0 + tx];
    }
    __syncthreads();
    #pragma unroll
    for (int r = 0; r < 4; r++) {
        int i = ty + r * 8;
        float v = tile[tx][i];
        size_t row = (size_t)m * 512 + n0 + i;
        int kk = k0 + tx;
        int ph = permw(kk >> 1) * 2 + (kk & 1);
        wh[row * 512 + ph] = __float2half_rn(v);
    }
}

__global__ void pack_b(const float* __restrict__ bq, const float* __restrict__ bk,
                       const float* __restrict__ bv, float* __restrict__ bqkv) {
    int idx = blockIdx.x * 1024 + threadIdx.x;
    if (idx >= LL * 1536) return;
    int l = idx / 1536, r = idx % 1536;
    bqkv[idx] = (r < 512) ? bq[l * 512 + r] : (r < 1024) ? bk[l * 512 + r - 512] : bv[l * 512 + r - 1024];
}

// ---------------- embedding (+ permuted fp16 copy) ----------------
__global__ void embed_kernel(const int* __restrict__ tok, const float* __restrict__ wte,
                             const float* __restrict__ wpe, float* __restrict__ x,
                             __half* __restrict__ xh) {
    int row = blockIdx.x;
    int tid = threadIdx.x;
    int tkn = __ldg(tok + row);
    int t = row & (TT - 1);
    float4 a = ((const float4*)(wte + (size_t)tkn * CC))[tid];
    float4 p = ((const float4*)(wpe + (size_t)t * CC))[tid];
    float4 o;
    o.x = a.x + p.x; o.y = a.y + p.y; o.z = a.z + p.z; o.w = a.w + p.w;
    ((float4*)(x + (size_t)row * CC))[tid] = o;
    uint32_t* hp = (uint32_t*)(xh + (size_t)row * CC);
    hp[permw(2 * tid)]     = pk2(o.x, o.y);
    hp[permw(2 * tid + 1)] = pk2(o.z, o.w);
}

// ---------------- fp16 HMMA GEMM: A via smem pipeline, B via register LDG prefetch ----------------
__global__ __launch_bounds__(256, 2)
void gemm_mma(const __half* __restrict__ A, const __half* __restrict__ Wh,
              int w_row_base, const float* __restrict__ bias, const float* __restrict__ res,
              float* __restrict__ out, __half* __restrict__ outh, int ldout) {
    extern __shared__ unsigned char smem_raw[];
    const int tid = threadIdx.x;
    const int lane = tid & 31;
    const int wid = tid >> 5;
    const int g = lane >> 2, tg = lane & 3;
    const int warp_m = wid & 1;
    const int warp_n = wid >> 1;
    const int mbase = blockIdx.y * 128;
    const int nb = blockIdx.x * 128;

    const uint32_t sbase = smem_u32(smem_raw);

    // A cp.async loader: thread -> rows (r0, r0+64) x one swizzled 16B chunk
    const int r0 = tid >> 2;
    const int c16 = tid & 3;
    const uint32_t so0 = sbase + (uint32_t)(r0 * 64) + (uint32_t)((c16 ^ (r0 & 3)) << 4);
    const size_t arow0 = (size_t)(mbase + r0) * 512 + c16 * 8;

    // A fragment base (swizzled smem)
    const uint32_t axor = (uint32_t)((tg ^ (g & 3)) << 4);
    const uint32_t aBase = sbase + (uint32_t)((warp_m * 64 + g) * 64) + axor;

    // B fragment pointer in GMEM (K-permuted layout => contiguous 16B per chunk)
    const __half* wptr = Wh + (size_t)(w_row_base + nb + warp_n * 32 + g) * 512 + tg * 8;

    float acc[4][4][4];
    #pragma unroll
    for (int i = 0; i < 4; i++)
        #pragma unroll
        for (int j = 0; j < 4; j++)
            #pragma unroll
            for (int q = 0; q < 4; q++) acc[i][j][q] = 0.f;

    auto ldgB = [&](int c, uint4* r) {
        #pragma unroll
        for (int nf = 0; nf < 4; nf++)
            r[nf] = *(const uint4*)(wptr + (size_t)nf * 8 * 512 + c * 32);
    };

    auto issueA = [&](int buf, int mc) {
        const int k0 = mc * 64;
        const uint32_t sb = so0 + (uint32_t)buf * AMST_B;
        cpa16(sb,                  A + arow0 + k0);
        cpa16(sb + 4096,           A + arow0 + 64 * 512 + k0);
        cpa16(sb + ASUB_B,         A + arow0 + k0 + 32);
        cpa16(sb + ASUB_B + 4096,  A + arow0 + 64 * 512 + k0 + 32);
        cpa_commit();
    };

    uint4 bA[4], bB[4];
    ldgB(0, bA);
    issueA(0, 0);
    issueA(1, 1);

    #pragma unroll 1
    for (int cc = 0; cc < 4; cc++) {
        // macro 2cc (buffer 0): sub-chunks 4cc, 4cc+1
        asm volatile("cp.async.wait_group 1;");
        __syncthreads();
        ldgB(4 * cc + 1, bB);
        compute_stage<0>(aBase, bA, acc);
        ldgB(4 * cc + 2, bA);
        compute_stage<ASUB_B>(aBase, bB, acc);
        __syncthreads();
        if (cc < 3) issueA(0, 2 * cc + 2);
        // macro 2cc+1 (buffer 1): sub-chunks 4cc+2, 4cc+3
        if (cc < 3) asm volatile("cp.async.wait_group 1;");
        else        asm volatile("cp.async.wait_group 0;");
        __syncthreads();
        ldgB(4 * cc + 3, bB);
        compute_stage<AMST_B>(aBase, bA, acc);
        if (cc < 3) ldgB(4 * cc + 4, bA);
        compute_stage<AMST_B + ASUB_B>(aBase, bB, acc);
        __syncthreads();
        if (cc < 3) issueA(1, 2 * cc + 3);
    }

    // --- epilogue ---
    if (outh) {
        #pragma unroll
        for (int nf = 0; nf < 4; nf++) {
            int col = nb + warp_n * 32 + nf * 8 + tg * 2;
            float2 b2 = *(const float2*)(bias + col);
            #pragma unroll
            for (int mf = 0; mf < 4; mf++) {
                int row = mbase + warp_m * 64 + mf * 16 + g;
                *(uint32_t*)(outh + (size_t)row * ldout + col) =
                    pk2(acc[mf][nf][0] + b2.x, acc[mf][nf][1] + b2.y);
                *(uint32_t*)(outh + (size_t)(row + 8) * ldout + col) =
                    pk2(acc[mf][nf][2] + b2.x, acc[mf][nf][3] + b2.y);
            }
        }
    } else {
        #pragma unroll
        for (int nf = 0; nf < 4; nf++) {
            int col = nb + warp_n * 32 + nf * 8 + tg * 2;
            float2 b2 = *(const float2*)(bias + col);
            #pragma unroll
            for (int mf = 0; mf < 4; mf++) {
                int row = mbase + warp_m * 64 + mf * 16 + g;
                float2 o0, o1;
                o0.x = acc[mf][nf][0] + b2.x; o0.y = acc[mf][nf][1] + b2.y;
                o1.x = acc[mf][nf][2] + b2.x; o1.y = acc[mf][nf][3] + b2.y;
                if (res) {
                    float2 r0v = *(const float2*)(res + (size_t)row * CC + col);
                    float2 r1v = *(const float2*)(res + (size_t)(row + 8) * CC + col);
                    o0.x += r0v.x; o0.y += r0v.y;
                    o1.x += r1v.x; o1.y += r1v.y;
                }
                *(float2*)(out + (size_t)row * ldout + col) = o0;
                *(float2*)(out + (size_t)(row + 8) * ldout + col) = o1;
            }
        }
    }
}

// ---------------- attention: one warp per position, syncwarp only ----------------
__global__ __launch_bounds__(256)
void attn_kernel(const __half* __restrict__ qkv, __half* __restrict__ hh) {
    __shared__ uint32_t sq[8][784];
    int w = threadIdx.x >> 5;
    int l = threadIdx.x & 31;
    int r = blockIdx.x * 8 + w;

    const uint32_t* src = (const uint32_t*)(qkv + (size_t)r * 1536);
    uint32_t* s = sq[w];
    #pragma unroll
    for (int it = 0; it < 8; it++)
        s[it * 33 + l] = src[it * 32 + l];
    #pragma unroll
    for (int it = 0; it < 8; it++)
        s[264 + it * 33 + l] = src[256 + it * 32 + l];
    #pragma unroll
    for (int it = 0; it < 8; it++)
        s[528 + it * 32 + l] = src[512 + it * 32 + l];
    __syncwarp();

    int g = l & 7, hb = l >> 3;
    float s1 = 0.f, s2 = 0.f;
    #pragma unroll
    for (int i = 0; i < 32; i++) {
        float2 kf = up2(s[264 + g * 33 + i]);
        float2 q1 = up2(s[hb * 33 + i]);
        float2 q2 = up2(s[(hb + 4) * 33 + i]);
        s1 += q1.x * kf.x + q1.y * kf.y;
        s2 += q2.x * kf.x + q2.y * kf.y;
    }
    s1 *= 0.125f; s2 *= 0.125f;

    float m1 = s1, m2 = s2;
    #pragma unroll
    for (int o = 1; o < 8; o <<= 1) {
        m1 = fmaxf(m1, __shfl_xor_sync(0xffffffffu, m1, o, 8));
        m2 = fmaxf(m2, __shfl_xor_sync(0xffffffffu, m2, o, 8));
    }
    float e1 = expf(s1 - m1), e2 = expf(s2 - m2);
    float t1 = e1, t2 = e2;
    #pragma unroll
    for (int o = 1; o < 8; o <<= 1) {
        t1 += __shfl_xor_sync(0xffffffffu, t1, o, 8);
        t2 += __shfl_xor_sync(0xffffffffu, t2, o, 8);
    }
    float a1 = e1 / t1, a2 = e2 / t2;

    float acc1[8] = {0,0,0,0,0,0,0,0}, acc2[8] = {0,0,0,0,0,0,0,0};
    #pragma unroll
    for (int g2 = 0; g2 < 8; g2++) {
        float b1 = __shfl_sync(0xffffffffu, a1, g2, 8);
        float b2 = __shfl_sync(0xffffffffu, a2, g2, 8);
        #pragma unroll
        for (int jj = 0; jj < 4; jj++) {
            float2 vf = up2(s[528 + g2 * 32 + g * 4 + jj]);
            acc1[2 * jj]     += b1 * vf.x;
            acc1[2 * jj + 1] += b1 * vf.y;
            acc2[2 * jj]     += b2 * vf.x;
            acc2[2 * jj + 1] += b2 * vf.y;
        }
    }

    uint32_t* hbase = (uint32_t*)(hh + (size_t)r * CC);
    uint32_t* hp1 = hbase + (hb * 2 + (g >> 2)) * 16 + (g & 3);
    hp1[0]  = pk2(acc1[0], acc1[1]);
    hp1[4]  = pk2(acc1[2], acc1[3]);
    hp1[8]  = pk2(acc1[4], acc1[5]);
    hp1[12] = pk2(acc1[6], acc1[7]);
    uint32_t* hp2 = hbase + ((hb + 4) * 2 + (g >> 2)) * 16 + (g & 3);
    hp2[0]  = pk2(acc2[0], acc2[1]);
    hp2[4]  = pk2(acc2[2], acc2[3]);
    hp2[8]  = pk2(acc2[4], acc2[5]);
    hp2[12] = pk2(acc2[6], acc2[7]);
}

// ---------------- LayerNorm (warp/row) with permuted fp16 copy ----------------
__global__ void ln_kernel(const float* __restrict__ y, const float* __restrict__ g,
                          const float* __restrict__ b, float* __restrict__ xo,
                          __half* __restrict__ xh) {
    int warp = threadIdx.x >> 5;
    int lane = threadIdx.x & 31;
    size_t row = (size_t)blockIdx.x * 8 + warp;

    const float4* yp = (const float4*)(y + row * CC);
    float4 v[4];
    float s = 0.f, s2 = 0.f;
    #pragma unroll
    for (int i = 0; i < 4; i++) {
        v[i] = yp[lane + 32 * i];
        s  += v[i].x + v[i].y + v[i].z + v[i].w;
        s2 += v[i].x * v[i].x + v[i].y * v[i].y + v[i].z * v[i].z + v[i].w * v[i].w;
    }
    #pragma unroll
    for (int o = 16; o; o >>= 1) {
        s  += __shfl_xor_sync(0xffffffffu, s, o);
        s2 += __shfl_xor_sync(0xffffffffu, s2, o);
    }
    float mean = s * (1.f / 512.f);
    float var = s2 * (1.f / 512.f) - mean * mean;
    float rstd = rsqrtf(var + 1e-5f);

    float4* xp = (float4*)(xo + row * CC);
    uint32_t* hp = (uint32_t*)(xh + row * CC);
    const float4* gp = (const float4*)g;
    const float4* bp = (const float4*)b;
    #pragma unroll
    for (int i = 0; i < 4; i++) {
        int i2 = lane + 32 * i;
        float4 gg = gp[i2], bb = bp[i2], o;
        o.x = (v[i].x - mean) * rstd * gg.x + bb.x;
        o.y = (v[i].y - mean) * rstd * gg.y + bb.y;
        o.z = (v[i].z - mean) * rstd * gg.z + bb.z;
        o.w = (v[i].w - mean) * rstd * gg.w + bb.w;
        xp[i2] = o;
        hp[permw(2 * i2)]     = pk2(o.x, o.y);
        hp[permw(2 * i2 + 1)] = pk2(o.z, o.w);
    }
}

// ---------------- LM head + loss ----------------
__global__ void lmhead_kernel(const float* __restrict__ x, const float* __restrict__ Wlm,
                              const float* __restrict__ blm, float* __restrict__ logits) {
    int warp = threadIdx.x >> 5;
    int lane = threadIdx.x & 31;
    size_t row = (size_t)blockIdx.x * 8 + warp;

    float p[VV];
    #pragma unroll
    for (int vv = 0; vv < VV; vv++) p[vv] = 0.f;
    const float* xr = x + row * CC;
    for (int kk = lane; kk < CC; kk += 32) {
        float xv = xr[kk];
        const float* wrow = Wlm + (size_t)kk * VV;
        #pragma unroll
        for (int vv = 0; vv < VV; vv++) p[vv] += xv * wrow[vv];
    }
    #pragma unroll
    for (int vv = 0; vv < VV; vv++)
        #pragma unroll
        for (int o = 16; o; o >>= 1) p[vv] += __shfl_xor_sync(0xffffffffu, p[vv], o);
    if (lane == 0) {
        float* lp = logits + row * VV;
        #pragma unroll
        for (int vv = 0; vv < VV; vv++) lp[vv] = p[vv] + blm[vv];
    }
}

__global__ void loss_kernel(const float* __restrict__ logits, const int* __restrict__ label,
                            float* __restrict__ out_loss) {
    __shared__ float sdata[512];
    int b = threadIdx.x;
    const float* lg = logits + ((size_t)b * TT + (TT - 1)) * VV;
    float m = lg[0];
    #pragma unroll
    for (int vv = 1; vv < VV; vv++) m = fmaxf(m, lg[vv]);
    float s = 0.f;
    #pragma unroll
    for (int vv = 0; vv < VV; vv++) s += expf(lg[vv] - m);
    float lse = m + logf(s);
    sdata[b] = -(lg[label[b]] - lse);
    __syncthreads();
    for (int st = 256; st; st >>= 1) {
        if (b < st) sdata[b] += sdata[b + st];
        __syncthreads();
    }
    if (b == 0) *out_loss = sdata[0] * (1.f / BB);
}

// ---------------- host ----------------
extern "C" void kernel_launch(void* const* d_in, const int* in_sizes, int n_in,
                              void* d_out, int out_size) {
    const int*   tok   = (const int*)d_in[0];
    const int*   label = (const int*)d_in[1];
    const float* wte   = (const float*)d_in[2];
    const float* wpe   = (const float*)d_in[3];
    const float* Wq    = (const float*)d_in[4];
    const float* bq    = (const float*)d_in[5];
    const float* Wk    = (const float*)d_in[6];
    const float* bk    = (const float*)d_in[7];
    const float* Wv    = (const float*)d_in[8];
    const float* bv    = (const float*)d_in[9];
    const float* Wo    = (const float*)d_in[10];
    const float* bo    = (const float*)d_in[11];
    const float* ln_g  = (const float*)d_in[12];
    const float* ln_b  = (const float*)d_in[13];
    const float* Wlm   = (const float*)d_in[14];
    const float* blm   = (const float*)d_in[15];
    float* out = (float*)d_out;

    unsigned char* base = nullptr;
    cudaGetSymbolAddress((void**)&base, g_scratch);
    float* x     = (float*)(base + OFF_X);
    __half* qkvh = (__half*)(base + OFF_QKVH);
    float* y     = (float*)(base + OFF_Y);
    __half* xh   = (__half*)(base + OFF_XH);
    __half* hh   = (__half*)(base + OFF_HHI);
    __half* wh   = (__half*)(base + OFF_WH);
    float* bqkv  = (float*)(base + OFF_BQKV);

    static bool attr_set = false;
    if (!attr_set) {
        cudaFuncSetAttribute(gemm_mma, cudaFuncAttributeMaxDynamicSharedMemorySize, GEMM_SMEM);
        attr_set = true;
    }

    prep_w<<<dim3(16, 16, 24), dim3(32, 8)>>>(Wq, Wk, Wv, Wo, wh);
    pack_b<<<9, 1024>>>(bq, bk, bv, bqkv);

    embed_kernel<<<MM, 128>>>(tok, wte, wpe, x, xh);

    for (int l = 0; l < LL; l++) {
        gemm_mma<<<dim3(12, MM / 128), 256, GEMM_SMEM>>>(xh, wh,
            l * 2048, bqkv + l * 1536, nullptr, nullptr, qkvh, 1536);
        attn_kernel<<<MM / 8, 256>>>(qkvh, hh);
        gemm_mma<<<dim3(4, MM / 128), 256, GEMM_SMEM>>>(hh, wh,
            l * 2048 + 1536, bo + l * 512, x, y, nullptr, 512);
        ln_kernel<<<MM / 8, 256>>>(y, ln_g + (size_t)l * CC, ln_b + (size_t)l * CC, x, xh);
    }

    lmhead_kernel<<<MM / 8, 256>>>(x, Wlm, blm, out);
    if (out_size >= MM * VV + 1)
        loss_kernel<<<1, 512>>>(out, label, out + (MM * VV));
}